// round 3
// baseline (speedup 1.0000x reference)
#include <cuda_runtime.h>
#include <cstdint>

#define UNITS  512
#define NIN    256
#define NBATCH 512
#define JT 8           // j-columns per CTA
#define BT 32          // batches per CTA
#define NTHR 128       // 16 batch-groups x 8 j

// ---------------- device scratch (static, no runtime allocation) -------------
__device__ float4 RPd[UNITS*UNITS];     // recurrent params {s, c, Wh, WEh}
__device__ float4 SPd[NIN*UNITS];       // sensory params
__device__ float2 NSdT[UNITS*NBATCH/2]; // sensory num, transposed [j][b2]
__device__ float2 DSdT[UNITS*NBATCH/2]; // sensory den, transposed
__device__ float  VTa[UNITS*NBATCH];    // v transposed [i][b], ping
__device__ float  VTb[UNITS*NBATCH];    // v transposed, pong
__device__ float  XTd[NIN*NBATCH];      // x transposed [i][b]
__device__ float  CGc_[UNITS];          // cm + gleak + sum_i Wh   (recurrent)
__device__ float  CNc_[UNITS];          // gleak*vleak + sum_i WEh (recurrent)
__device__ float  SWs_[UNITS];          // sum_i Wh   (sensory)
__device__ float  SWEs_[UNITS];         // sum_i WEh  (sensory)

// sigmoid(sigma*(v-mu)) = 0.5 + 0.5*tanh(0.5*sigma*v - 0.5*sigma*mu)
// act = W*sigmoid = Wh*tanh(u) + Wh, Wh = 0.5*W; constant halves folded into
// per-j column sums applied once in the epilogue.

__global__ void prep_r(const float* __restrict__ mu, const float* __restrict__ sg,
                       const float* __restrict__ W,  const float* __restrict__ er) {
    int idx = blockIdx.x*blockDim.x + threadIdx.x;
    if (idx < UNITS*UNITS) {
        float s = sg[idx], m = mu[idx], w = W[idx], e = er[idx];
        RPd[idx] = make_float4(0.5f*s, -0.5f*s*m, 0.5f*w, 0.5f*w*e);
    }
}

__global__ void prep_s(const float* __restrict__ mu, const float* __restrict__ sg,
                       const float* __restrict__ W,  const float* __restrict__ er) {
    int idx = blockIdx.x*blockDim.x + threadIdx.x;
    if (idx < NIN*UNITS) {
        float s = sg[idx], m = mu[idx], w = W[idx], e = er[idx];
        SPd[idx] = make_float4(0.5f*s, -0.5f*s*m, 0.5f*w, 0.5f*w*e);
    }
}

// coalesced column sums: lane = j, 8 i-rows per warp-row, smem reduce
__global__ __launch_bounds__(256) void colsums(const float* __restrict__ cm,
                                               const float* __restrict__ gl,
                                               const float* __restrict__ vl) {
    __shared__ float sm[8][32][4];
    int tx = threadIdx.x & 31;
    int ty = threadIdx.x >> 5;
    int j  = blockIdx.x*32 + tx;

    float rw = 0.f, rwe = 0.f, sw = 0.f, swe = 0.f;
    for (int i = ty; i < UNITS; i += 8) { float4 p = RPd[i*UNITS + j]; rw += p.z; rwe += p.w; }
    for (int i = ty; i < NIN;   i += 8) { float4 p = SPd[i*UNITS + j]; sw += p.z; swe += p.w; }
    sm[ty][tx][0] = rw; sm[ty][tx][1] = rwe; sm[ty][tx][2] = sw; sm[ty][tx][3] = swe;
    __syncthreads();
    if (ty == 0) {
        for (int r = 1; r < 8; r++) {
            rw += sm[r][tx][0]; rwe += sm[r][tx][1];
            sw += sm[r][tx][2]; swe += sm[r][tx][3];
        }
        SWs_[j]  = sw;
        SWEs_[j] = swe;
        CGc_[j]  = cm[j] + gl[j] + rw;
        CNc_[j]  = gl[j]*vl[j] + rwe;
    }
}

// transpose state [b][u] -> VTa [u][b]
__global__ __launch_bounds__(256) void transpose_state(const float* __restrict__ src) {
    __shared__ float tile[32][33];
    int ibase = blockIdx.x*32, bbase = blockIdx.y*32;
    int tx = threadIdx.x & 31, ty = threadIdx.x >> 5;
    #pragma unroll
    for (int k = 0; k < 4; k++)
        tile[ty + k*8][tx] = src[(bbase + ty + k*8)*UNITS + ibase + tx];
    __syncthreads();
    #pragma unroll
    for (int k = 0; k < 4; k++)
        VTa[(ibase + ty + k*8)*NBATCH + bbase + tx] = tile[tx][ty + k*8];
}

// transpose VTb [u][b] -> out [b][u]  (final output)
__global__ __launch_bounds__(256) void transpose_out(float* __restrict__ dst) {
    __shared__ float tile[32][33];
    int ibase = blockIdx.x*32, bbase = blockIdx.y*32;
    int tx = threadIdx.x & 31, ty = threadIdx.x >> 5;
    #pragma unroll
    for (int k = 0; k < 4; k++)
        tile[ty + k*8][tx] = VTb[(ibase + ty + k*8)*NBATCH + bbase + tx];
    __syncthreads();
    #pragma unroll
    for (int k = 0; k < 4; k++)
        dst[(bbase + ty + k*8)*UNITS + ibase + tx] = tile[tx][ty + k*8];
}

// transpose+affine inputs [b][in] -> XTd [in][b]
__global__ __launch_bounds__(256) void transpose_x(const float* __restrict__ inp,
                                                   const float* __restrict__ iw,
                                                   const float* __restrict__ ib) {
    __shared__ float tile[32][33];
    int ibase = blockIdx.x*32, bbase = blockIdx.y*32;
    int tx = threadIdx.x & 31, ty = threadIdx.x >> 5;
    #pragma unroll
    for (int k = 0; k < 4; k++)
        tile[ty + k*8][tx] = inp[(bbase + ty + k*8)*NIN + ibase + tx];
    __syncthreads();
    #pragma unroll
    for (int k = 0; k < 4; k++) {
        int i = ibase + ty + k*8;
        XTd[i*NBATCH + bbase + tx] = fmaf(tile[tx][ty + k*8], iw[i], ib[i]);
    }
}

__device__ __forceinline__ float tanh_apx(float x) {
    float y;
    asm("tanh.approx.f32 %0, %1;" : "=f"(y) : "f"(x));
    return y;
}

// ---------------- sensory synapse sums ---------------------------------------
__global__ __launch_bounds__(NTHR) void sensory_k() {
    int tx = threadIdx.x & (JT-1);
    int bg = threadIdx.x >> 3;              // 0..15
    int j  = blockIdx.x*JT + tx;
    int bb2 = blockIdx.y*(BT/2) + bg;       // float2 batch index

    const float4* __restrict__ rp  = SPd + j;
    const float2* __restrict__ vp2 = reinterpret_cast<const float2*>(XTd) + bb2;

    float num0 = 0.f, num1 = 0.f, den0 = 0.f, den1 = 0.f;
    #pragma unroll 16
    for (int i = 0; i < NIN; i++) {
        float4 p  = rp[i*UNITS];
        float2 vv = vp2[i*(NBATCH/2)];
        float h0 = tanh_apx(fmaf(p.x, vv.x, p.y));
        float h1 = tanh_apx(fmaf(p.x, vv.y, p.y));
        den0 = fmaf(p.z, h0, den0); num0 = fmaf(p.w, h0, num0);
        den1 = fmaf(p.z, h1, den1); num1 = fmaf(p.w, h1, num1);
    }
    float sw = SWs_[j], swe = SWEs_[j];
    NSdT[j*(NBATCH/2) + bb2] = make_float2(num0 + swe, num1 + swe);
    DSdT[j*(NBATCH/2) + bb2] = make_float2(den0 + sw,  den1 + sw);
}

// ---------------- one ODE unfold step -----------------------------------------
__global__ __launch_bounds__(NTHR) void unfold_k(const float* __restrict__ cm,
                                                 int in_sel) {
    const float* vin   = (in_sel == 1) ? VTa : VTb;
    float2*      vout2 = reinterpret_cast<float2*>((in_sel == 1) ? VTb : VTa);

    int tx = threadIdx.x & (JT-1);
    int bg = threadIdx.x >> 3;
    int j  = blockIdx.x*JT + tx;
    int bb2 = blockIdx.y*(BT/2) + bg;

    const float4* __restrict__ rp  = RPd + j;
    const float2* __restrict__ vp2 = reinterpret_cast<const float2*>(vin) + bb2;

    float num0 = 0.f, num1 = 0.f, den0 = 0.f, den1 = 0.f;
    #pragma unroll 16
    for (int i = 0; i < UNITS; i++) {
        float4 p  = rp[i*UNITS];
        float2 vv = vp2[i*(NBATCH/2)];
        float h0 = tanh_apx(fmaf(p.x, vv.x, p.y));
        float h1 = tanh_apx(fmaf(p.x, vv.y, p.y));
        den0 = fmaf(p.z, h0, den0); num0 = fmaf(p.w, h0, num0);
        den1 = fmaf(p.z, h1, den1); num1 = fmaf(p.w, h1, num1);
    }

    float cgj = CGc_[j], cnj = CNc_[j], cmj = cm[j];
    float2 ns = NSdT[j*(NBATCH/2) + bb2];
    float2 ds = DSdT[j*(NBATCH/2) + bb2];
    float2 vpv = vp2[j*(NBATCH/2)];

    float r0 = __fdividef(fmaf(cmj, vpv.x, cnj + ns.x + num0), cgj + ds.x + den0);
    float r1 = __fdividef(fmaf(cmj, vpv.y, cnj + ns.y + num1), cgj + ds.y + den1);

    vout2[j*(NBATCH/2) + bb2] = make_float2(r0, r1);
}

// ---------------- launch ------------------------------------------------------
extern "C" void kernel_launch(void* const* d_in, const int* in_sizes, int n_in,
                              void* d_out, int out_size) {
    const float* inputs = (const float*)d_in[0];
    const float* state  = (const float*)d_in[1];
    const float* iw     = (const float*)d_in[2];
    const float* ib     = (const float*)d_in[3];
    const float* smu    = (const float*)d_in[4];
    const float* ssig   = (const float*)d_in[5];
    const float* sW     = (const float*)d_in[6];
    const float* serev  = (const float*)d_in[7];
    const float* rmu    = (const float*)d_in[8];
    const float* rsig   = (const float*)d_in[9];
    const float* rW     = (const float*)d_in[10];
    const float* rerev  = (const float*)d_in[11];
    const float* vleak  = (const float*)d_in[12];
    const float* gleak  = (const float*)d_in[13];
    const float* cm     = (const float*)d_in[14];
    float* out = (float*)d_out;

    prep_r<<<(UNITS*UNITS + 255)/256, 256>>>(rmu, rsig, rW, rerev);
    prep_s<<<(NIN*UNITS + 255)/256, 256>>>(smu, ssig, sW, serev);
    colsums<<<UNITS/32, 256>>>(cm, gleak, vleak);
    transpose_state<<<dim3(UNITS/32, NBATCH/32), 256>>>(state);
    transpose_x<<<dim3(NIN/32, NBATCH/32), 256>>>(inputs, iw, ib);

    dim3 grid(UNITS/JT, NBATCH/BT);   // 64 x 16 = 1024 CTAs
    sensory_k<<<grid, NTHR>>>();

    // 6 unfolds: VTa(state) -> VTb -> VTa -> VTb -> VTa -> VTb
    unfold_k<<<grid, NTHR>>>(cm, 1);
    unfold_k<<<grid, NTHR>>>(cm, 2);
    unfold_k<<<grid, NTHR>>>(cm, 1);
    unfold_k<<<grid, NTHR>>>(cm, 2);
    unfold_k<<<grid, NTHR>>>(cm, 1);
    unfold_k<<<grid, NTHR>>>(cm, 2);

    transpose_out<<<dim3(UNITS/32, NBATCH/32), 256>>>(out);
}

// round 4
// speedup vs baseline: 1.3946x; 1.3946x over previous
#include <cuda_runtime.h>
#include <cstdint>

#define UNITS  512
#define NIN    256
#define NBATCH 512
#define JT 32          // j-columns per CTA
#define BT 16          // batches per CTA
#define NB 4           // batches per thread
#define NTHR 128
#define VSTR 20        // smem row stride (floats): float4-aligned, conflict-benign
#define CH 8           // prefetch chunk (param float4s in flight)

// ---------------- device scratch (static, no runtime allocation) -------------
__device__ float4 RPd[UNITS*UNITS];   // recurrent params {s, c, Wh, WEh}
__device__ float4 SPd[NIN*UNITS];     // sensory params
__device__ float  NSd[NBATCH*UNITS];  // sensory numerator term [b][j]
__device__ float  DSd[NBATCH*UNITS];  // sensory denominator term [b][j]
__device__ float  VBa[NBATCH*UNITS];  // v ping  [b][u]
__device__ float  VBb[NBATCH*UNITS];  // v pong  [b][u]
__device__ float  CGc_[UNITS];        // cm + gleak + sum_i Wh   (recurrent)
__device__ float  CNc_[UNITS];        // gleak*vleak + sum_i WEh (recurrent)
__device__ float  SWs_[UNITS];        // sum_i Wh   (sensory)
__device__ float  SWEs_[UNITS];       // sum_i WEh  (sensory)

// sigmoid(sigma*(v-mu)) = 0.5 + 0.5*tanh(0.5*sigma*v - 0.5*sigma*mu)
// act = W*sigmoid = Wh*tanh(u) + Wh with Wh = 0.5*W; the constant "+Wh" halves
// are folded into per-j column sums applied once in the epilogue.

__global__ void prep_r(const float* __restrict__ mu, const float* __restrict__ sg,
                       const float* __restrict__ W,  const float* __restrict__ er) {
    int idx = blockIdx.x*blockDim.x + threadIdx.x;
    if (idx < UNITS*UNITS) {
        float s = sg[idx], m = mu[idx], w = W[idx], e = er[idx];
        RPd[idx] = make_float4(0.5f*s, -0.5f*s*m, 0.5f*w, 0.5f*w*e);
    }
}

__global__ void prep_s(const float* __restrict__ mu, const float* __restrict__ sg,
                       const float* __restrict__ W,  const float* __restrict__ er) {
    int idx = blockIdx.x*blockDim.x + threadIdx.x;
    if (idx < NIN*UNITS) {
        float s = sg[idx], m = mu[idx], w = W[idx], e = er[idx];
        SPd[idx] = make_float4(0.5f*s, -0.5f*s*m, 0.5f*w, 0.5f*w*e);
    }
}

// coalesced column sums: lane = j, 8 i-rows per warp-row, smem reduce
__global__ __launch_bounds__(256) void colsums(const float* __restrict__ cm,
                                               const float* __restrict__ gl,
                                               const float* __restrict__ vl) {
    __shared__ float sm[8][32][4];
    int tx = threadIdx.x & 31;
    int ty = threadIdx.x >> 5;
    int j  = blockIdx.x*32 + tx;

    float rw = 0.f, rwe = 0.f, sw = 0.f, swe = 0.f;
    for (int i = ty; i < UNITS; i += 8) { float4 p = RPd[i*UNITS + j]; rw += p.z; rwe += p.w; }
    for (int i = ty; i < NIN;   i += 8) { float4 p = SPd[i*UNITS + j]; sw += p.z; swe += p.w; }
    sm[ty][tx][0] = rw; sm[ty][tx][1] = rwe; sm[ty][tx][2] = sw; sm[ty][tx][3] = swe;
    __syncthreads();
    if (ty == 0) {
        for (int r = 1; r < 8; r++) {
            rw += sm[r][tx][0]; rwe += sm[r][tx][1];
            sw += sm[r][tx][2]; swe += sm[r][tx][3];
        }
        SWs_[j]  = sw;
        SWEs_[j] = swe;
        CGc_[j]  = cm[j] + gl[j] + rw;
        CNc_[j]  = gl[j]*vl[j] + rwe;
    }
}

__device__ __forceinline__ float tanh_apx(float x) {
    float y;
    asm("tanh.approx.f32 %0, %1;" : "=f"(y) : "f"(x));
    return y;
}

// ---------------- sensory synapse sums ---------------------------------------
__global__ __launch_bounds__(NTHR) void sensory_k(const float* __restrict__ inp,
                                                  const float* __restrict__ iw,
                                                  const float* __restrict__ ib) {
    __shared__ float xs[NIN*VSTR];     // 20 KB
    int jbase = blockIdx.x * JT;
    int bbase = blockIdx.y * BT;
    int t = threadIdx.x;

    // stage x = inputs*input_w + input_b, transposed: xs[i*VSTR + b]
    for (int idx = t; idx < BT*NIN; idx += NTHR) {
        int b = idx >> 8;              // NIN = 256
        int i = idx & (NIN-1);
        xs[i*VSTR + b] = fmaf(inp[(bbase + b)*NIN + i], iw[i], ib[i]);
    }
    __syncthreads();

    int tx = t & 31;
    int bg = t >> 5;                   // warp-uniform
    int j  = jbase + tx;

    const float4* __restrict__ rp = SPd + j;
    float num0=0.f,num1=0.f,num2=0.f,num3=0.f;
    float den0=0.f,den1=0.f,den2=0.f,den3=0.f;

    float4 PA[CH], PB[CH];
    #pragma unroll
    for (int k = 0; k < CH; k++) PA[k] = rp[k*UNITS];

    const int NC = NIN/CH;             // 32 chunks
    #pragma unroll 1
    for (int c = 0; c < NC; c += 2) {
        { const float4* q = rp + (size_t)(c+1)*CH*UNITS;
          #pragma unroll
          for (int k = 0; k < CH; k++) PB[k] = q[(size_t)k*UNITS]; }
        #pragma unroll
        for (int k = 0; k < CH; k++) {
            float4 p  = PA[k];
            float4 vv = *reinterpret_cast<const float4*>(xs + (c*CH + k)*VSTR + bg*NB);
            float h0 = tanh_apx(fmaf(p.x, vv.x, p.y));
            float h1 = tanh_apx(fmaf(p.x, vv.y, p.y));
            float h2 = tanh_apx(fmaf(p.x, vv.z, p.y));
            float h3 = tanh_apx(fmaf(p.x, vv.w, p.y));
            den0 = fmaf(p.z, h0, den0); num0 = fmaf(p.w, h0, num0);
            den1 = fmaf(p.z, h1, den1); num1 = fmaf(p.w, h1, num1);
            den2 = fmaf(p.z, h2, den2); num2 = fmaf(p.w, h2, num2);
            den3 = fmaf(p.z, h3, den3); num3 = fmaf(p.w, h3, num3);
        }
        { int cn = (c + 2 < NC) ? (c + 2) : 0;          // wrap: harmless, L1-hot
          const float4* q = rp + (size_t)cn*CH*UNITS;
          #pragma unroll
          for (int k = 0; k < CH; k++) PA[k] = q[(size_t)k*UNITS]; }
        #pragma unroll
        for (int k = 0; k < CH; k++) {
            float4 p  = PB[k];
            float4 vv = *reinterpret_cast<const float4*>(xs + ((c+1)*CH + k)*VSTR + bg*NB);
            float h0 = tanh_apx(fmaf(p.x, vv.x, p.y));
            float h1 = tanh_apx(fmaf(p.x, vv.y, p.y));
            float h2 = tanh_apx(fmaf(p.x, vv.z, p.y));
            float h3 = tanh_apx(fmaf(p.x, vv.w, p.y));
            den0 = fmaf(p.z, h0, den0); num0 = fmaf(p.w, h0, num0);
            den1 = fmaf(p.z, h1, den1); num1 = fmaf(p.w, h1, num1);
            den2 = fmaf(p.z, h2, den2); num2 = fmaf(p.w, h2, num2);
            den3 = fmaf(p.z, h3, den3); num3 = fmaf(p.w, h3, num3);
        }
    }

    float sw = SWs_[j], swe = SWEs_[j];
    float nn[NB] = {num0,num1,num2,num3};
    float dd[NB] = {den0,den1,den2,den3};
    #pragma unroll
    for (int k = 0; k < NB; k++) {
        int b = bbase + bg*NB + k;
        NSd[b*UNITS + j] = nn[k] + swe;
        DSd[b*UNITS + j] = dd[k] + sw;
    }
}

// ---------------- one ODE unfold step -----------------------------------------
__global__ __launch_bounds__(NTHR) void unfold_k(const float* __restrict__ vext,
                                                 const float* __restrict__ cm,
                                                 float* __restrict__ dout,
                                                 int in_sel, int out_sel) {
    __shared__ float vs[UNITS*VSTR];   // 40 KB
    const float* vin = (in_sel  == 0) ? vext : (in_sel  == 1 ? VBa : VBb);
    float*      vout = (out_sel == 0) ? dout : (out_sel == 1 ? VBa : VBb);

    int jbase = blockIdx.x * JT;
    int bbase = blockIdx.y * BT;
    int t = threadIdx.x;

    // stage v transposed: vs[i*VSTR + b]
    for (int idx = t; idx < BT*UNITS; idx += NTHR) {
        int b = idx >> 9;              // UNITS = 512
        int i = idx & (UNITS-1);
        vs[i*VSTR + b] = vin[(bbase + b)*UNITS + i];
    }
    __syncthreads();

    int tx = t & 31;
    int bg = t >> 5;
    int j  = jbase + tx;

    const float4* __restrict__ rp = RPd + j;
    float num0=0.f,num1=0.f,num2=0.f,num3=0.f;
    float den0=0.f,den1=0.f,den2=0.f,den3=0.f;

    float4 PA[CH], PB[CH];
    #pragma unroll
    for (int k = 0; k < CH; k++) PA[k] = rp[k*UNITS];

    const int NC = UNITS/CH;           // 64 chunks
    #pragma unroll 1
    for (int c = 0; c < NC; c += 2) {
        { const float4* q = rp + (size_t)(c+1)*CH*UNITS;
          #pragma unroll
          for (int k = 0; k < CH; k++) PB[k] = q[(size_t)k*UNITS]; }
        #pragma unroll
        for (int k = 0; k < CH; k++) {
            float4 p  = PA[k];
            float4 vv = *reinterpret_cast<const float4*>(vs + (c*CH + k)*VSTR + bg*NB);
            float h0 = tanh_apx(fmaf(p.x, vv.x, p.y));
            float h1 = tanh_apx(fmaf(p.x, vv.y, p.y));
            float h2 = tanh_apx(fmaf(p.x, vv.z, p.y));
            float h3 = tanh_apx(fmaf(p.x, vv.w, p.y));
            den0 = fmaf(p.z, h0, den0); num0 = fmaf(p.w, h0, num0);
            den1 = fmaf(p.z, h1, den1); num1 = fmaf(p.w, h1, num1);
            den2 = fmaf(p.z, h2, den2); num2 = fmaf(p.w, h2, num2);
            den3 = fmaf(p.z, h3, den3); num3 = fmaf(p.w, h3, num3);
        }
        { int cn = (c + 2 < NC) ? (c + 2) : 0;          // wrap: harmless, L1-hot
          const float4* q = rp + (size_t)cn*CH*UNITS;
          #pragma unroll
          for (int k = 0; k < CH; k++) PA[k] = q[(size_t)k*UNITS]; }
        #pragma unroll
        for (int k = 0; k < CH; k++) {
            float4 p  = PB[k];
            float4 vv = *reinterpret_cast<const float4*>(vs + ((c+1)*CH + k)*VSTR + bg*NB);
            float h0 = tanh_apx(fmaf(p.x, vv.x, p.y));
            float h1 = tanh_apx(fmaf(p.x, vv.y, p.y));
            float h2 = tanh_apx(fmaf(p.x, vv.z, p.y));
            float h3 = tanh_apx(fmaf(p.x, vv.w, p.y));
            den0 = fmaf(p.z, h0, den0); num0 = fmaf(p.w, h0, num0);
            den1 = fmaf(p.z, h1, den1); num1 = fmaf(p.w, h1, num1);
            den2 = fmaf(p.z, h2, den2); num2 = fmaf(p.w, h2, num2);
            den3 = fmaf(p.z, h3, den3); num3 = fmaf(p.w, h3, num3);
        }
    }

    float cgj = CGc_[j], cnj = CNc_[j], cmj = cm[j];
    float nn[NB] = {num0,num1,num2,num3};
    float dd[NB] = {den0,den1,den2,den3};
    #pragma unroll
    for (int k = 0; k < NB; k++) {
        int b = bbase + bg*NB + k;
        float vp    = vs[j*VSTR + (bg*NB + k)];
        float numer = fmaf(cmj, vp, cnj + NSd[b*UNITS + j] + nn[k]);
        float denom = cgj + DSd[b*UNITS + j] + dd[k];
        vout[b*UNITS + j] = __fdividef(numer, denom);
    }
}

// ---------------- launch ------------------------------------------------------
extern "C" void kernel_launch(void* const* d_in, const int* in_sizes, int n_in,
                              void* d_out, int out_size) {
    const float* inputs = (const float*)d_in[0];
    const float* state  = (const float*)d_in[1];
    const float* iw     = (const float*)d_in[2];
    const float* ib     = (const float*)d_in[3];
    const float* smu    = (const float*)d_in[4];
    const float* ssig   = (const float*)d_in[5];
    const float* sW     = (const float*)d_in[6];
    const float* serev  = (const float*)d_in[7];
    const float* rmu    = (const float*)d_in[8];
    const float* rsig   = (const float*)d_in[9];
    const float* rW     = (const float*)d_in[10];
    const float* rerev  = (const float*)d_in[11];
    const float* vleak  = (const float*)d_in[12];
    const float* gleak  = (const float*)d_in[13];
    const float* cm     = (const float*)d_in[14];
    float* out = (float*)d_out;

    prep_r<<<(UNITS*UNITS + 255)/256, 256>>>(rmu, rsig, rW, rerev);
    prep_s<<<(NIN*UNITS + 255)/256, 256>>>(smu, ssig, sW, serev);
    colsums<<<UNITS/32, 256>>>(cm, gleak, vleak);

    dim3 grid(UNITS/JT, NBATCH/BT);   // 16 x 32 = 512 CTAs
    sensory_k<<<grid, NTHR>>>(inputs, iw, ib);

    // 6 unfolds: state -> VBa -> VBb -> VBa -> VBb -> VBa -> d_out
    unfold_k<<<grid, NTHR>>>(state,   cm, nullptr, 0, 1);
    unfold_k<<<grid, NTHR>>>(nullptr, cm, nullptr, 1, 2);
    unfold_k<<<grid, NTHR>>>(nullptr, cm, nullptr, 2, 1);
    unfold_k<<<grid, NTHR>>>(nullptr, cm, nullptr, 1, 2);
    unfold_k<<<grid, NTHR>>>(nullptr, cm, nullptr, 2, 1);
    unfold_k<<<grid, NTHR>>>(nullptr, cm, out,     1, 0);
}